// round 1
// baseline (speedup 1.0000x reference)
#include <cuda_runtime.h>

// Each row: 9 floats in, 3 floats out. HBM-bound streaming problem.
// Strategy: stage 256 rows (2304 floats) per block through shared memory
// with coalesced float4 loads/stores; per-row smem access at stride 9
// (conflict-free since gcd(9,32)=1). Compute is trivial integer/FP logic.

constexpr int TPB = 256;  // rows per block == threads per block

__global__ void __launch_bounds__(TPB) concat_kernel(
    const float* __restrict__ in, float* __restrict__ out, int n_rows)
{
    __shared__ float s_in[TPB * 9];
    __shared__ float s_out[TPB * 3];

    const long long base = (long long)blockIdx.x * TPB;
    const bool full = (base + TPB) <= n_rows;

    if (full) {
        // Coalesced float4 load: 576 float4s. base*9*4 bytes is 16B aligned
        // (256*36 = 9216 bytes per block).
        const float4* in4 = reinterpret_cast<const float4*>(in + base * 9);
        float4* s4 = reinterpret_cast<float4*>(s_in);
        #pragma unroll
        for (int i = threadIdx.x; i < TPB * 9 / 4; i += TPB)
            s4[i] = in4[i];
    } else {
        // Tail path (not hit for N=2^23 but kept for safety)
        for (int i = threadIdx.x; i < TPB * 9; i += TPB) {
            long long g = base * 9 + i;
            s_in[i] = (g < (long long)n_rows * 9) ? in[g] : 0.0f;
        }
    }
    __syncthreads();

    const int r = threadIdx.x;
    const long long row = base + r;

    if (row < n_rows) {
        float x[9];
        #pragma unroll
        for (int k = 0; k < 9; k++) x[k] = s_in[r * 9 + k];

        // Per-vector: mi = ties ? 0 : CONVERT[argmax], CONVERT = {1,0,-1}
        int mi[3];
        #pragma unroll
        for (int j = 0; j < 3; j++) {
            float a0 = x[3 * j + 0], a1 = x[3 * j + 1], a2 = x[3 * j + 2];
            float mx = fmaxf(a0, fmaxf(a1, a2));
            int cnt = (a0 == mx) + (a1 == mx) + (a2 == mx);
            // first-occurrence argmax
            int am = (a0 >= a1 && a0 >= a2) ? 0 : (a1 >= a2 ? 1 : 2);
            mi[j] = (cnt > 1) ? 0 : (1 - am);
        }

        int calc = abs(mi[1]) * (mi[0] + mi[1] + mi[2]);

        // keep[j]: sign(calc) matches sign(mi[j]) including zero case
        float vecs[9];
        #pragma unroll
        for (int j = 0; j < 3; j++) {
            bool keep = ((calc > 0) & (mi[j] > 0)) |
                        ((calc < 0) & (mi[j] < 0)) |
                        ((calc == 0) & (mi[j] == 0));
            #pragma unroll
            for (int k = 0; k < 3; k++)
                vecs[3 * j + k] = keep ? x[3 * j + k] : 0.0f;
        }

        int idx = (calc == 0) ? 1 : ((calc >= 1) ? 0 : 2);

        float v0 = vecs[0 * 3 + idx];
        float v1 = vecs[1 * 3 + idx];
        float v2 = vecs[2 * 3 + idx];

        // first-occurrence argmax over the three vals
        int win = 0;
        float best = v0;
        if (v1 > best) { best = v1; win = 1; }
        if (v2 > best) { best = v2; win = 2; }

        #pragma unroll
        for (int k = 0; k < 3; k++)
            s_out[r * 3 + k] = vecs[win * 3 + k];
    }
    __syncthreads();

    if (full) {
        // Coalesced float4 store: 192 float4s. base*3*4 = 3072 B aligned.
        const float4* s4 = reinterpret_cast<const float4*>(s_out);
        float4* out4 = reinterpret_cast<float4*>(out + base * 3);
        #pragma unroll
        for (int i = threadIdx.x; i < TPB * 3 / 4; i += TPB)
            out4[i] = s4[i];
    } else {
        for (int i = threadIdx.x; i < TPB * 3; i += TPB) {
            long long g = base * 3 + i;
            if (g < (long long)n_rows * 3) out[g] = s_out[i];
        }
    }
}

extern "C" void kernel_launch(void* const* d_in, const int* in_sizes, int n_in,
                              void* d_out, int out_size)
{
    const float* in = (const float*)d_in[0];
    float* out = (float*)d_out;
    int n_rows = in_sizes[0] / 9;
    int grid = (n_rows + TPB - 1) / TPB;
    concat_kernel<<<grid, TPB>>>(in, out, n_rows);
}

// round 2
// speedup vs baseline: 1.3869x; 1.3869x over previous
#include <cuda_runtime.h>

// 4 rows per thread: 144 B in = 9 aligned float4, 48 B out = 3 aligned float4.
// No shared memory, no syncs. Compute is a slim branchless select chain.

constexpr int TPB = 256;

__device__ __forceinline__ void process_row(const float* __restrict__ x,
                                            float* __restrict__ o)
{
    // mi[j] = +1 if x[3j] is strict unique max, -1 if x[3j+2] is, else 0
    int mi[3];
#pragma unroll
    for (int j = 0; j < 3; j++) {
        float a0 = x[3*j], a1 = x[3*j+1], a2 = x[3*j+2];
        bool q0 = (a0 > a1) && (a0 > a2);
        bool q2 = (a2 > a0) && (a2 > a1);
        mi[j] = (int)q0 - (int)q2;
    }

    int calc = ((mi[1] < 0) ? -mi[1] : mi[1]) * (mi[0] + mi[1] + mi[2]);
    int sc   = (calc > 0) - (calc < 0);   // sign(calc)

    // keep_j <=> mi[j] == sign(calc); masked vectors
    float m[9];
#pragma unroll
    for (int j = 0; j < 3; j++) {
        bool keep = (mi[j] == sc);
#pragma unroll
        for (int k = 0; k < 3; k++)
            m[3*j + k] = keep ? x[3*j + k] : 0.0f;
    }

    // idx = 1 - sc  (calc==0 -> 1, calc>0 -> 0, calc<0 -> 2)
    float v0, v1, v2;
    if (sc == 0)      { v0 = m[1]; v1 = m[4]; v2 = m[7]; }
    else if (sc > 0)  { v0 = m[0]; v1 = m[3]; v2 = m[6]; }
    else              { v0 = m[2]; v1 = m[5]; v2 = m[8]; }

    // first-occurrence argmax over (v0, v1, v2)
    bool b1 = (v1 > v0);
    float best01 = b1 ? v1 : v0;
    bool b2 = (v2 > best01);

#pragma unroll
    for (int k = 0; k < 3; k++) {
        float t01 = b1 ? m[3 + k] : m[k];
        o[k] = b2 ? m[6 + k] : t01;
    }
}

__global__ void __launch_bounds__(TPB) concat_kernel4(
    const float4* __restrict__ in4, float4* __restrict__ out4, int n4)
{
    int t = blockIdx.x * blockDim.x + threadIdx.x;
    if (t >= n4) return;

    // Load 4 rows = 9 float4 (base 144*t bytes, 16B-aligned)
    float x[36];
    const float4* p = in4 + (size_t)t * 9;
#pragma unroll
    for (int i = 0; i < 9; i++) {
        float4 v = __ldg(&p[i]);
        x[4*i + 0] = v.x; x[4*i + 1] = v.y;
        x[4*i + 2] = v.z; x[4*i + 3] = v.w;
    }

    float o[12];
#pragma unroll
    for (int r = 0; r < 4; r++)
        process_row(x + 9*r, o + 3*r);

    // Store 4 rows = 3 float4 (base 48*t bytes, 16B-aligned)
    float4* q = out4 + (size_t)t * 3;
#pragma unroll
    for (int i = 0; i < 3; i++) {
        float4 v;
        v.x = o[4*i + 0]; v.y = o[4*i + 1];
        v.z = o[4*i + 2]; v.w = o[4*i + 3];
        q[i] = v;
    }
}

// Scalar tail kernel for n_rows % 4 != 0 (not hit for N = 2^23)
__global__ void concat_tail(const float* __restrict__ in,
                            float* __restrict__ out,
                            int row_start, int n_rows)
{
    int row = row_start + blockIdx.x * blockDim.x + threadIdx.x;
    if (row >= n_rows) return;
    float x[9];
#pragma unroll
    for (int k = 0; k < 9; k++) x[k] = in[(size_t)row * 9 + k];
    float o[3];
    process_row(x, o);
#pragma unroll
    for (int k = 0; k < 3; k++) out[(size_t)row * 3 + k] = o[k];
}

extern "C" void kernel_launch(void* const* d_in, const int* in_sizes, int n_in,
                              void* d_out, int out_size)
{
    const float* in = (const float*)d_in[0];
    float* out = (float*)d_out;
    int n_rows = in_sizes[0] / 9;

    int n4 = n_rows / 4;
    if (n4 > 0) {
        int grid = (n4 + TPB - 1) / TPB;
        concat_kernel4<<<grid, TPB>>>((const float4*)in, (float4*)out, n4);
    }
    int rem = n_rows - n4 * 4;
    if (rem > 0) {
        concat_tail<<<1, 128>>>(in, out, n4 * 4, n_rows);
    }
}

// round 3
// speedup vs baseline: 1.6126x; 1.1627x over previous
#include <cuda_runtime.h>

// 1024 rows per 256-thread block, staged through shared memory.
// Global side: fully coalesced float4 (4 wavefronts per LDG/STG.128).
// Smem side: LDS.128 @144B stride and STS.128 @48B stride, both provably
// bank-conflict-free. Compute: slim branchless select chain (4 rows/thread).

constexpr int TPB = 256;
constexpr int RPT = 4;                    // rows per thread
constexpr int RPB = TPB * RPT;            // 1024 rows per block

__device__ __forceinline__ void process_row(const float* __restrict__ x,
                                            float* __restrict__ o)
{
    // mi[j] = +1 if x[3j] strict unique max, -1 if x[3j+2] strict unique max
    int mi[3];
#pragma unroll
    for (int j = 0; j < 3; j++) {
        float a0 = x[3*j], a1 = x[3*j+1], a2 = x[3*j+2];
        bool q0 = (a0 > a1) && (a0 > a2);
        bool q2 = (a2 > a0) && (a2 > a1);
        mi[j] = (int)q0 - (int)q2;
    }

    int calc = ((mi[1] < 0) ? -mi[1] : mi[1]) * (mi[0] + mi[1] + mi[2]);
    int sc   = (calc > 0) - (calc < 0);   // sign(calc)

    float m[9];
#pragma unroll
    for (int j = 0; j < 3; j++) {
        bool keep = (mi[j] == sc);
#pragma unroll
        for (int k = 0; k < 3; k++)
            m[3*j + k] = keep ? x[3*j + k] : 0.0f;
    }

    // idx = 1 - sc
    float v0, v1, v2;
    if (sc == 0)      { v0 = m[1]; v1 = m[4]; v2 = m[7]; }
    else if (sc > 0)  { v0 = m[0]; v1 = m[3]; v2 = m[6]; }
    else              { v0 = m[2]; v1 = m[5]; v2 = m[8]; }

    bool b1 = (v1 > v0);
    float best01 = b1 ? v1 : v0;
    bool b2 = (v2 > best01);

#pragma unroll
    for (int k = 0; k < 3; k++) {
        float t01 = b1 ? m[3 + k] : m[k];
        o[k] = b2 ? m[6 + k] : t01;
    }
}

__global__ void __launch_bounds__(TPB) concat_smem(
    const float4* __restrict__ in4, float4* __restrict__ out4)
{
    __shared__ float4 s_in[RPB * 9 / 4];    // 36 KB
    __shared__ float4 s_out[RPB * 3 / 4];   // 12 KB

    const int tid = threadIdx.x;
    const size_t base4_in = (size_t)blockIdx.x * (RPB * 9 / 4);

    // Coalesced global -> smem: 9 float4 per thread
#pragma unroll
    for (int i = 0; i < 9; i++)
        s_in[i * TPB + tid] = in4[base4_in + i * TPB + tid];
    __syncthreads();

    // Compute 4 rows: read 9 float4 at lane stride 9 float4 (conflict-free)
    float x[36];
#pragma unroll
    for (int i = 0; i < 9; i++) {
        float4 v = s_in[tid * 9 + i];
        x[4*i+0] = v.x; x[4*i+1] = v.y; x[4*i+2] = v.z; x[4*i+3] = v.w;
    }

    float o[12];
#pragma unroll
    for (int r = 0; r < RPT; r++)
        process_row(x + 9*r, o + 3*r);

    // Stage output: 3 float4 at lane stride 3 float4 (conflict-free)
#pragma unroll
    for (int i = 0; i < 3; i++) {
        float4 v;
        v.x = o[4*i+0]; v.y = o[4*i+1]; v.z = o[4*i+2]; v.w = o[4*i+3];
        s_out[tid * 3 + i] = v;
    }
    __syncthreads();

    // Coalesced smem -> global: 3 float4 per thread
    const size_t base4_out = (size_t)blockIdx.x * (RPB * 3 / 4);
#pragma unroll
    for (int i = 0; i < 3; i++)
        out4[base4_out + i * TPB + tid] = s_out[i * TPB + tid];
}

// Scalar tail for n_rows % 1024 != 0 (not hit for N = 2^23)
__global__ void concat_tail(const float* __restrict__ in,
                            float* __restrict__ out,
                            int row_start, int n_rows)
{
    int row = row_start + blockIdx.x * blockDim.x + threadIdx.x;
    if (row >= n_rows) return;
    float x[9];
#pragma unroll
    for (int k = 0; k < 9; k++) x[k] = in[(size_t)row * 9 + k];
    float o[3];
    process_row(x, o);
#pragma unroll
    for (int k = 0; k < 3; k++) out[(size_t)row * 3 + k] = o[k];
}

extern "C" void kernel_launch(void* const* d_in, const int* in_sizes, int n_in,
                              void* d_out, int out_size)
{
    const float* in = (const float*)d_in[0];
    float* out = (float*)d_out;
    int n_rows = in_sizes[0] / 9;

    int nfull = n_rows / RPB;
    if (nfull > 0)
        concat_smem<<<nfull, TPB>>>((const float4*)in, (float4*)out);

    int done = nfull * RPB;
    int rem = n_rows - done;
    if (rem > 0) {
        int grid = (rem + 255) / 256;
        concat_tail<<<grid, 256>>>(in, out, done, n_rows);
    }
}

// round 4
// speedup vs baseline: 1.6282x; 1.0097x over previous
#include <cuda_runtime.h>
#include <cstdint>

// 1024 rows / 256-thread block. Input staged via cp.async (LDGSTS, L1-bypass)
// into 36KB smem; same buffer reused for output staging after a sync.
// 6 CTAs/SM target (216KB smem, <=42 regs via launch_bounds).

constexpr int TPB = 256;
constexpr int RPT = 4;
constexpr int RPB = TPB * RPT;            // 1024 rows per block
constexpr int IN4 = RPB * 9 / 4;          // 2304 float4 = 36 KB
constexpr int OUT4 = RPB * 3 / 4;         // 768 float4 (reuses same buffer)

__device__ __forceinline__ void process_row(const float* __restrict__ x,
                                            float* __restrict__ o)
{
    int mi[3];
#pragma unroll
    for (int j = 0; j < 3; j++) {
        float a0 = x[3*j], a1 = x[3*j+1], a2 = x[3*j+2];
        bool q0 = (a0 > a1) && (a0 > a2);
        bool q2 = (a2 > a0) && (a2 > a1);
        mi[j] = (int)q0 - (int)q2;
    }

    int calc = ((mi[1] < 0) ? -mi[1] : mi[1]) * (mi[0] + mi[1] + mi[2]);
    int sc   = (calc > 0) - (calc < 0);

    float m[9];
#pragma unroll
    for (int j = 0; j < 3; j++) {
        bool keep = (mi[j] == sc);
#pragma unroll
        for (int k = 0; k < 3; k++)
            m[3*j + k] = keep ? x[3*j + k] : 0.0f;
    }

    float v0, v1, v2;
    if (sc == 0)      { v0 = m[1]; v1 = m[4]; v2 = m[7]; }
    else if (sc > 0)  { v0 = m[0]; v1 = m[3]; v2 = m[6]; }
    else              { v0 = m[2]; v1 = m[5]; v2 = m[8]; }

    bool b1 = (v1 > v0);
    float best01 = b1 ? v1 : v0;
    bool b2 = (v2 > best01);

#pragma unroll
    for (int k = 0; k < 3; k++) {
        float t01 = b1 ? m[3 + k] : m[k];
        o[k] = b2 ? m[6 + k] : t01;
    }
}

__global__ void __launch_bounds__(TPB, 6) concat_smem(
    const float4* __restrict__ in4, float4* __restrict__ out4)
{
    __shared__ float4 s[IN4];             // 36 KB, reused for output

    const int tid = threadIdx.x;
    const size_t base_in = (size_t)blockIdx.x * IN4;

    // Inbound staging via cp.async.cg (16B, L1-bypass): 9 ops/thread,
    // no register round-trip.
#pragma unroll
    for (int i = 0; i < 9; i++) {
        uint32_t dst = (uint32_t)__cvta_generic_to_shared(&s[i * TPB + tid]);
        const float4* src = in4 + base_in + i * TPB + tid;
        asm volatile("cp.async.cg.shared.global [%0], [%1], 16;\n"
                     :: "r"(dst), "l"(src) : "memory");
    }
    asm volatile("cp.async.commit_group;\n" ::: "memory");
    asm volatile("cp.async.wait_group 0;\n" ::: "memory");
    __syncthreads();

    // Pull this thread's 4 rows: 9 LDS.128 at 144B lane stride (conflict-free)
    float x[36];
#pragma unroll
    for (int i = 0; i < 9; i++) {
        float4 v = s[tid * 9 + i];
        x[4*i+0] = v.x; x[4*i+1] = v.y; x[4*i+2] = v.z; x[4*i+3] = v.w;
    }
    __syncthreads();   // all reads done before buffer reuse

    float o[12];
#pragma unroll
    for (int r = 0; r < RPT; r++)
        process_row(x + 9*r, o + 3*r);

    // Stage output into the SAME buffer: 3 STS.128 at 48B stride (conflict-free)
#pragma unroll
    for (int i = 0; i < 3; i++) {
        float4 v;
        v.x = o[4*i+0]; v.y = o[4*i+1]; v.z = o[4*i+2]; v.w = o[4*i+3];
        s[tid * 3 + i] = v;
    }
    __syncthreads();

    // Coalesced smem -> global
    const size_t base_out = (size_t)blockIdx.x * OUT4;
#pragma unroll
    for (int i = 0; i < 3; i++)
        out4[base_out + i * TPB + tid] = s[i * TPB + tid];
}

// Scalar tail for n_rows % 1024 != 0 (not hit for N = 2^23)
__global__ void concat_tail(const float* __restrict__ in,
                            float* __restrict__ out,
                            int row_start, int n_rows)
{
    int row = row_start + blockIdx.x * blockDim.x + threadIdx.x;
    if (row >= n_rows) return;
    float x[9];
#pragma unroll
    for (int k = 0; k < 9; k++) x[k] = in[(size_t)row * 9 + k];
    float o[3];
    process_row(x, o);
#pragma unroll
    for (int k = 0; k < 3; k++) out[(size_t)row * 3 + k] = o[k];
}

extern "C" void kernel_launch(void* const* d_in, const int* in_sizes, int n_in,
                              void* d_out, int out_size)
{
    const float* in = (const float*)d_in[0];
    float* out = (float*)d_out;
    int n_rows = in_sizes[0] / 9;

    int nfull = n_rows / RPB;
    if (nfull > 0)
        concat_smem<<<nfull, TPB>>>((const float4*)in, (float4*)out);

    int done = nfull * RPB;
    int rem = n_rows - done;
    if (rem > 0) {
        int grid = (rem + 255) / 256;
        concat_tail<<<grid, 256>>>(in, out, done, n_rows);
    }
}

// round 5
// speedup vs baseline: 1.6407x; 1.0077x over previous
#include <cuda_runtime.h>
#include <cstdint>

// 1024 rows / 256-thread block. Bulk-TMA staging both directions:
//   in : one cp.async.bulk (36 KB) gmem->smem, mbarrier-completed
//   out: one cp.async.bulk (12 KB) smem->gmem, bulk_group
// Compute: 4 rows/thread, conflict-free LDS.128 / STS.128, slim select chain.

constexpr int TPB = 256;
constexpr int RPT = 4;
constexpr int RPB = TPB * RPT;               // 1024 rows per block
constexpr int IN4 = RPB * 9 / 4;             // 2304 float4 = 36 KB
constexpr int IN_BYTES = IN4 * 16;           // 36864
constexpr int OUT_BYTES = RPB * 3 * 4;       // 12288

__device__ __forceinline__ void process_row(const float* __restrict__ x,
                                            float* __restrict__ o)
{
    int mi[3];
#pragma unroll
    for (int j = 0; j < 3; j++) {
        float a0 = x[3*j], a1 = x[3*j+1], a2 = x[3*j+2];
        bool q0 = (a0 > a1) && (a0 > a2);
        bool q2 = (a2 > a0) && (a2 > a1);
        mi[j] = (int)q0 - (int)q2;
    }

    int calc = ((mi[1] < 0) ? -mi[1] : mi[1]) * (mi[0] + mi[1] + mi[2]);
    int sc   = (calc > 0) - (calc < 0);

    float m[9];
#pragma unroll
    for (int j = 0; j < 3; j++) {
        bool keep = (mi[j] == sc);
#pragma unroll
        for (int k = 0; k < 3; k++)
            m[3*j + k] = keep ? x[3*j + k] : 0.0f;
    }

    float v0, v1, v2;
    if (sc == 0)      { v0 = m[1]; v1 = m[4]; v2 = m[7]; }
    else if (sc > 0)  { v0 = m[0]; v1 = m[3]; v2 = m[6]; }
    else              { v0 = m[2]; v1 = m[5]; v2 = m[8]; }

    bool b1 = (v1 > v0);
    float best01 = b1 ? v1 : v0;
    bool b2 = (v2 > best01);

#pragma unroll
    for (int k = 0; k < 3; k++) {
        float t01 = b1 ? m[3 + k] : m[k];
        o[k] = b2 ? m[6 + k] : t01;
    }
}

__global__ void __launch_bounds__(TPB, 6) concat_tma(
    const float4* __restrict__ in4, float4* __restrict__ out4)
{
    __shared__ float4 s[IN4];                  // 36 KB, reused for output
    __shared__ __align__(8) uint64_t mbar;

    const int tid = threadIdx.x;
    uint32_t mb = (uint32_t)__cvta_generic_to_shared(&mbar);
    uint32_t s_base = (uint32_t)__cvta_generic_to_shared(s);

    if (tid == 0) {
        asm volatile("mbarrier.init.shared.b64 [%0], %1;"
                     :: "r"(mb), "r"(1) : "memory");
    }
    __syncthreads();

    if (tid == 0) {
        const float4* src = in4 + (size_t)blockIdx.x * IN4;
        asm volatile("mbarrier.arrive.expect_tx.shared.b64 _, [%0], %1;"
                     :: "r"(mb), "r"(IN_BYTES) : "memory");
        asm volatile(
            "cp.async.bulk.shared::cta.global.mbarrier::complete_tx::bytes "
            "[%0], [%1], %2, [%3];"
            :: "r"(s_base), "l"(src), "r"(IN_BYTES), "r"(mb) : "memory");
    }

    // All threads wait for the bulk load (phase 0)
    {
        uint32_t done;
        asm volatile(
            "{\n\t.reg .pred p;\n\t"
            "mbarrier.try_wait.parity.shared.b64 p, [%1], 0;\n\t"
            "selp.b32 %0, 1, 0, p;\n\t}"
            : "=r"(done) : "r"(mb) : "memory");
        while (!done) {
            asm volatile(
                "{\n\t.reg .pred p;\n\t"
                "mbarrier.try_wait.parity.shared.b64 p, [%1], 0;\n\t"
                "selp.b32 %0, 1, 0, p;\n\t}"
                : "=r"(done) : "r"(mb) : "memory");
        }
    }
    __syncthreads();

    // Pull this thread's 4 rows: 9 LDS.128 @144B lane stride (conflict-free)
    float x[36];
#pragma unroll
    for (int i = 0; i < 9; i++) {
        float4 v = s[tid * 9 + i];
        x[4*i+0] = v.x; x[4*i+1] = v.y; x[4*i+2] = v.z; x[4*i+3] = v.w;
    }
    __syncthreads();   // all reads complete before buffer reuse

    float o[12];
#pragma unroll
    for (int r = 0; r < RPT; r++)
        process_row(x + 9*r, o + 3*r);

    // Stage output into same buffer: 3 STS.128 @48B stride (conflict-free)
#pragma unroll
    for (int i = 0; i < 3; i++) {
        float4 v;
        v.x = o[4*i+0]; v.y = o[4*i+1]; v.z = o[4*i+2]; v.w = o[4*i+3];
        s[tid * 3 + i] = v;
    }
    __syncthreads();

    // Single bulk store: 12 KB smem -> gmem
    if (tid == 0) {
        float4* dst = out4 + (size_t)blockIdx.x * (OUT_BYTES / 16);
        asm volatile("fence.proxy.async.shared::cta;" ::: "memory");
        asm volatile(
            "cp.async.bulk.global.shared::cta.bulk_group [%0], [%1], %2;"
            :: "l"(dst), "r"(s_base), "r"(OUT_BYTES) : "memory");
        asm volatile("cp.async.bulk.commit_group;" ::: "memory");
        asm volatile("cp.async.bulk.wait_group.read 0;" ::: "memory");
    }
}

// Scalar tail for n_rows % 1024 != 0 (not hit for N = 2^23)
__global__ void concat_tail(const float* __restrict__ in,
                            float* __restrict__ out,
                            int row_start, int n_rows)
{
    int row = row_start + blockIdx.x * blockDim.x + threadIdx.x;
    if (row >= n_rows) return;
    float x[9];
#pragma unroll
    for (int k = 0; k < 9; k++) x[k] = in[(size_t)row * 9 + k];
    float o[3];
    process_row(x, o);
#pragma unroll
    for (int k = 0; k < 3; k++) out[(size_t)row * 3 + k] = o[k];
}

extern "C" void kernel_launch(void* const* d_in, const int* in_sizes, int n_in,
                              void* d_out, int out_size)
{
    const float* in = (const float*)d_in[0];
    float* out = (float*)d_out;
    int n_rows = in_sizes[0] / 9;

    int nfull = n_rows / RPB;
    if (nfull > 0)
        concat_tma<<<nfull, TPB>>>((const float4*)in, (float4*)out);

    int done = nfull * RPB;
    int rem = n_rows - done;
    if (rem > 0) {
        int grid = (rem + 255) / 256;
        concat_tail<<<grid, 256>>>(in, out, done, n_rows);
    }
}